// round 15
// baseline (speedup 1.0000x reference)
#include <cuda_runtime.h>
#include <cuda_bf16.h>

#define RDIM 256
#define SDIM 256
#define CH   32                  // rows per chunk
#define NCHUNK (RDIM / CH)       // 8
#define PSTR 260                 // padded row stride in floats (1040B, 16B-aligned)
#define BUFF (CH * PSTR)         // floats per buffer
#define NEG_INF (-1e30f)

__device__ __forceinline__ void consider(
    float v, int s, float &a0, int &x0, float &a1, int &x1, float &a2, int &x2)
{
    if (v > a2) {                          // rare after warm-up
        if (v > a0)      { a2 = a1; x2 = x1; a1 = a0; x1 = x0; a0 = v; x0 = s; }
        else if (v > a1) { a2 = a1; x2 = x1; a1 = v;  x1 = s; }
        else             { a2 = v;  x2 = s; }
    }
}

__global__ __launch_bounds__(512)
void ipm_kernel(const float* __restrict__ msm,
                const int* __restrict__ refm,     // bool promoted to int32
                const int* __restrict__ srcm,     // bool promoted to int32
                float* __restrict__ out_score,
                float* __restrict__ out_corr)     // bool output stored as float32
{
    extern __shared__ float stile[];              // 2 * BUFF floats = 66,560 B

    const int p   = blockIdx.x;
    const int tid = threadIdx.x;                  // 0..511

    const float* __restrict__ tile = msm + (size_t)p * RDIM * SDIM;
    float* __restrict__ oscore = out_score + (size_t)p * RDIM * SDIM;
    float* __restrict__ ocorr  = out_corr  + (size_t)p * RDIM * SDIM;

    // ---- prologue: start chunk 0 prefetch immediately -----------------------
    {
        const float4* gsrc = (const float4*)tile;     // chunk 0 = rows 0..31
        #pragma unroll
        for (int k = 0; k < 4; ++k) {
            int g  = tid + 512 * k;                   // 0..2047 float4s
            int rl = g >> 6, c4 = g & 63;
            unsigned dst = (unsigned)__cvta_generic_to_shared(&stile[rl * PSTR + 4 * c4]);
            asm volatile("cp.async.ca.shared.global [%0], [%1], 16;\n"
                         :: "r"(dst), "l"(gsrc + g));
        }
        asm volatile("cp.async.commit_group;\n");
    }

    // ---- zero-fill both output maps (fire-and-forget, drains under pipeline)
    {
        const float4 z4 = make_float4(0.f, 0.f, 0.f, 0.f);
        float4* zs = (float4*)oscore;
        float4* zc = (float4*)ocorr;
        #pragma unroll 8
        for (int i = tid; i < (RDIM * SDIM) / 4; i += 512) {
            zs[i] = z4;
            zc[i] = z4;
        }
    }

    // top-3 of RAW scores (exp is monotonic; applied to winners only).
    // tid<256: column t = tid.   tid>=256: row u = tid-256 (active in one chunk).
    float b0 = NEG_INF, b1 = NEG_INF, b2 = NEG_INF;
    int   j0 = 0,       j1 = 0,       j2 = 0;

    for (int c = 0; c < NCHUNK; ++c) {
        // prefetch chunk c+1 into the other buffer (that buffer was released
        // by the trailing __syncthreads of iteration c-1)
        if (c + 1 < NCHUNK) {
            const float4* gsrc = (const float4*)(tile + (size_t)((c + 1) * CH) * SDIM);
            float* buf = stile + ((c + 1) & 1) * BUFF;
            #pragma unroll
            for (int k = 0; k < 4; ++k) {
                int g  = tid + 512 * k;
                int rl = g >> 6, c4 = g & 63;
                unsigned dst = (unsigned)__cvta_generic_to_shared(&buf[rl * PSTR + 4 * c4]);
                asm volatile("cp.async.ca.shared.global [%0], [%1], 16;\n"
                             :: "r"(dst), "l"(gsrc + g));
            }
            asm volatile("cp.async.commit_group;\n");
            asm volatile("cp.async.wait_group 1;\n");   // chunk c arrived
        } else {
            asm volatile("cp.async.wait_group 0;\n");   // last chunk arrived
        }
        __syncthreads();                                 // all see chunk c

        const float* buf = stile + (c & 1) * BUFF;
        if (tid < 256) {
            // column t: 32 considers, conflict-free LDS (consecutive t)
            const int t = tid;
            #pragma unroll
            for (int rl = 0; rl < CH; ++rl)
                consider(buf[rl * PSTR + t], c * CH + rl, b0, j0, b1, j1, b2, j2);
        } else {
            const int u = tid - 256;                     // global row index
            if ((u >> 5) == c) {
                // this warp owns chunk c's 32 rows: full-row scan from smem
                const int rl = u & (CH - 1);
                const float4* __restrict__ srow = (const float4*)&buf[rl * PSTR];
                #pragma unroll 8
                for (int q4 = 0; q4 < SDIM / 4; ++q4) {
                    float4 q = srow[q4];
                    int s = 4 * q4;
                    consider(q.x, s + 0, b0, j0, b1, j1, b2, j2);
                    consider(q.y, s + 1, b0, j0, b1, j1, b2, j2);
                    consider(q.z, s + 2, b0, j0, b1, j1, b2, j2);
                    consider(q.w, s + 3, b0, j0, b1, j1, b2, j2);
                }
            }
        }
        __syncthreads();   // buffer c free for reuse by chunk c+2's prefetch
    }

    // ---------------- scatter (exp applied to the 3 winners only) ------------
    float vs[3] = {__expf(b0), __expf(b1), __expf(b2)};
    int   is[3] = {j0, j1, j2};

    if (tid < 256) {
        // Column t's top-3 along R
        const int t = tid;
        const bool ms = srcm[(size_t)p * SDIM + t] != 0;
        #pragma unroll
        for (int k = 0; k < 3; ++k) {
            int r = is[k];
            float v = vs[k];
            atomicAdd(&oscore[r * SDIM + t], 0.5f * v);
            if (v > 0.0f && ms && refm[(size_t)p * RDIM + r] != 0)
                ocorr[r * SDIM + t] = 1.0f;   // idempotent write, benign race
        }
    } else {
        // Row u's top-3 along S
        const int t = tid - 256;
        const bool mr = refm[(size_t)p * RDIM + t] != 0;
        #pragma unroll
        for (int k = 0; k < 3; ++k) {
            int s = is[k];
            float v = vs[k];
            atomicAdd(&oscore[t * SDIM + s], 0.5f * v);
            if (v > 0.0f && mr && srcm[(size_t)p * SDIM + s] != 0)
                ocorr[t * SDIM + s] = 1.0f;
        }
    }
}

extern "C" void kernel_launch(void* const* d_in, const int* in_sizes, int n_in,
                              void* d_out, int out_size)
{
    // metadata order: matching_score_map [P,R,S] f32, node_corr_scores [P] f32 (unused),
    //                 ref_knn_masks [P,R] bool->int32, src_knn_masks [P,S] bool->int32
    const float* msm  = (const float*)d_in[0];
    const int*   refm = (const int*)d_in[2];
    const int*   srcm = (const int*)d_in[3];

    const int P = in_sizes[1];                 // node_corr_scores has P elements
    float* out_score = (float*)d_out;
    float* out_corr  = out_score + (size_t)P * RDIM * SDIM;  // bool output as float32

    const int SMEM = 2 * BUFF * (int)sizeof(float);          // 66,560 B
    cudaFuncSetAttribute(ipm_kernel, cudaFuncAttributeMaxDynamicSharedMemorySize, SMEM);

    ipm_kernel<<<P, 512, SMEM>>>(msm, refm, srcm, out_score, out_corr);
}

// round 16
// speedup vs baseline: 1.8003x; 1.8003x over previous
#include <cuda_runtime.h>
#include <cuda_bf16.h>

#define RDIM 256
#define SDIM 256
#define CH   16                  // rows per chunk
#define NCHUNK (RDIM / CH)       // 16
#define PSTR 260                 // padded row stride in floats (1040B)
#define BUFF (CH * PSTR)         // 4160 floats per buffer
#define NEG_INF (-1e30f)

// Stable comparator: value desc, index asc on ties (matches jax top_k).
__device__ __forceinline__ bool better(float a, int i, float b, int j)
{
    return (a > b) || (a == b && i < j);
}

// Merge two stable-sorted triples -> top-3 in a. Validated R9/R12.
__device__ __forceinline__ void merge3(
    float &a0, int &i0, float &a1, int &i1, float &a2, int &i2,
    float b0, int j0, float b1, int j1, float b2, int j2)
{
    float o0, o1, o2; int p0, p1, p2;
    if (better(a0, i0, b0, j0)) { o0 = a0; p0 = i0; a0 = a1; i0 = i1; a1 = a2; i1 = i2; }
    else                        { o0 = b0; p0 = j0; b0 = b1; j0 = j1; b1 = b2; j1 = j2; }
    if (better(a0, i0, b0, j0)) { o1 = a0; p1 = i0; a0 = a1; i0 = i1; }
    else                        { o1 = b0; p1 = j0; b0 = b1; j0 = j1; }
    if (better(a0, i0, b0, j0)) { o2 = a0; p2 = i0; }
    else                        { o2 = b0; p2 = j0; }
    a0 = o0; i0 = p0; a1 = o1; i1 = p1; a2 = o2; i2 = p2;
}

// Sequential stable top-3 (strict >, ascending scan order).
__device__ __forceinline__ void consider(
    float v, int s, float &a0, int &x0, float &a1, int &x1, float &a2, int &x2)
{
    if (v > a2) {
        if (v > a0)      { a2 = a1; x2 = x1; a1 = a0; x1 = x0; a0 = v; x0 = s; }
        else if (v > a1) { a2 = a1; x2 = x1; a1 = v;  x1 = s; }
        else             { a2 = v;  x2 = s; }
    }
}

__global__ __launch_bounds__(512)
void ipm_kernel(const float* __restrict__ msm,
                const int* __restrict__ refm,
                const int* __restrict__ srcm,
                float* __restrict__ out_score,
                float* __restrict__ out_corr)
{
    extern __shared__ float stile[];              // 2 * BUFF floats = 33,280 B
    __shared__ float s_rv[RDIM][3];               // per-row top-3 values
    __shared__ int   s_ri[RDIM][3];               // per-row top-3 indices

    const int p   = blockIdx.x;
    const int tid = threadIdx.x;                  // 0..511

    const float* __restrict__ tile = msm + (size_t)p * RDIM * SDIM;
    float* __restrict__ oscore = out_score + (size_t)p * RDIM * SDIM;
    float* __restrict__ ocorr  = out_corr  + (size_t)p * RDIM * SDIM;

    // ---- prologue: prefetch chunk 0 (16 rows = 1024 float4, 2 per thread) ---
    {
        const float4* gsrc = (const float4*)tile;
        #pragma unroll
        for (int k = 0; k < 2; ++k) {
            int g  = tid + 512 * k;               // 0..1023
            int rl = g >> 6, c4 = g & 63;
            unsigned dst = (unsigned)__cvta_generic_to_shared(&stile[rl * PSTR + 4 * c4]);
            asm volatile("cp.async.ca.shared.global [%0], [%1], 16;\n"
                         :: "r"(dst), "l"(gsrc + g));
        }
        asm volatile("cp.async.commit_group;\n");
    }

    // ---- zero-fill both output maps (drains under the pipeline) -------------
    {
        const float4 z4 = make_float4(0.f, 0.f, 0.f, 0.f);
        float4* zs = (float4*)oscore;
        float4* zc = (float4*)ocorr;
        #pragma unroll 8
        for (int i = tid; i < (RDIM * SDIM) / 4; i += 512) {
            zs[i] = z4;
            zc[i] = z4;
        }
    }

    // column-half running triple (raw scores; exp at scatter)
    float b0 = NEG_INF, b1 = NEG_INF, b2 = NEG_INF;
    int   j0 = 0,       j1 = 0,       j2 = 0;

    const int u   = tid - 256;                    // row-half linear id
    const int rsl = u >> 4;                       // row slot 0..15 (row-half only)
    const int seg = u & 15;                       // segment 0..15 (16 cols each)

    for (int c = 0; c < NCHUNK; ++c) {
        if (c + 1 < NCHUNK) {
            const float4* gsrc = (const float4*)(tile + (size_t)((c + 1) * CH) * SDIM);
            float* buf = stile + ((c + 1) & 1) * BUFF;
            #pragma unroll
            for (int k = 0; k < 2; ++k) {
                int g  = tid + 512 * k;
                int rl = g >> 6, c4 = g & 63;
                unsigned dst = (unsigned)__cvta_generic_to_shared(&buf[rl * PSTR + 4 * c4]);
                asm volatile("cp.async.ca.shared.global [%0], [%1], 16;\n"
                             :: "r"(dst), "l"(gsrc + g));
            }
            asm volatile("cp.async.commit_group;\n");
            asm volatile("cp.async.wait_group 1;\n");
        } else {
            asm volatile("cp.async.wait_group 0;\n");
        }
        __syncthreads();                          // chunk c visible to all

        const float* buf = stile + (c & 1) * BUFF;
        if (tid < 256) {
            // column t: 16 considers, conflict-free
            const int t = tid;
            #pragma unroll
            for (int rl = 0; rl < CH; ++rl)
                consider(buf[rl * PSTR + t], c * CH + rl, b0, j0, b1, j1, b2, j2);
        } else {
            // row slot rsl, segment seg: 16 elements, ascending (stable)
            float a0 = NEG_INF, a1 = NEG_INF, a2 = NEG_INF;
            int   x0 = 0,       x1 = 0,       x2 = 0;
            const float4* srow = (const float4*)&buf[rsl * PSTR + seg * 16];
            #pragma unroll
            for (int q = 0; q < 4; ++q) {
                float4 v = srow[q];
                int s = seg * 16 + 4 * q;
                consider(v.x, s + 0, a0, x0, a1, x1, a2, x2);
                consider(v.y, s + 1, a0, x0, a1, x1, a2, x2);
                consider(v.z, s + 2, a0, x0, a1, x1, a2, x2);
                consider(v.w, s + 3, a0, x0, a1, x1, a2, x2);
            }
            // width-16 butterfly merge (stable) across the 16 segments
            #pragma unroll
            for (int off = 8; off >= 1; off >>= 1) {
                float c0 = __shfl_xor_sync(0xffffffffu, a0, off, 16);
                float c1 = __shfl_xor_sync(0xffffffffu, a1, off, 16);
                float c2 = __shfl_xor_sync(0xffffffffu, a2, off, 16);
                int   y0 = __shfl_xor_sync(0xffffffffu, x0, off, 16);
                int   y1 = __shfl_xor_sync(0xffffffffu, x1, off, 16);
                int   y2 = __shfl_xor_sync(0xffffffffu, x2, off, 16);
                merge3(a0, x0, a1, x1, a2, x2, c0, y0, c1, y1, c2, y2);
            }
            if (seg == 0) {
                int r = c * CH + rsl;
                s_rv[r][0] = a0; s_rv[r][1] = a1; s_rv[r][2] = a2;
                s_ri[r][0] = x0; s_ri[r][1] = x1; s_ri[r][2] = x2;
            }
        }
        __syncthreads();                          // buffer free for c+2 prefetch
    }

    // ---------------- scatter (exp on winners only) ---------------------------
    if (tid < 256) {
        const int t = tid;
        const bool ms = srcm[(size_t)p * SDIM + t] != 0;
        float vs[3] = {__expf(b0), __expf(b1), __expf(b2)};
        int   is[3] = {j0, j1, j2};
        #pragma unroll
        for (int k = 0; k < 3; ++k) {
            int r = is[k];
            float v = vs[k];
            atomicAdd(&oscore[r * SDIM + t], 0.5f * v);
            if (v > 0.0f && ms && refm[(size_t)p * RDIM + r] != 0)
                ocorr[r * SDIM + t] = 1.0f;       // idempotent, benign race
        }
    } else {
        const int t = tid - 256;
        const bool mr = refm[(size_t)p * RDIM + t] != 0;
        #pragma unroll
        for (int k = 0; k < 3; ++k) {
            int s = s_ri[t][k];
            float v = __expf(s_rv[t][k]);
            atomicAdd(&oscore[t * SDIM + s], 0.5f * v);
            if (v > 0.0f && mr && srcm[(size_t)p * SDIM + s] != 0)
                ocorr[t * SDIM + s] = 1.0f;
        }
    }
}

extern "C" void kernel_launch(void* const* d_in, const int* in_sizes, int n_in,
                              void* d_out, int out_size)
{
    const float* msm  = (const float*)d_in[0];
    const int*   refm = (const int*)d_in[2];
    const int*   srcm = (const int*)d_in[3];

    const int P = in_sizes[1];
    float* out_score = (float*)d_out;
    float* out_corr  = out_score + (size_t)P * RDIM * SDIM;

    const int SMEM = 2 * BUFF * (int)sizeof(float);   // 33,280 B dynamic
    cudaFuncSetAttribute(ipm_kernel, cudaFuncAttributeMaxDynamicSharedMemorySize, SMEM);

    ipm_kernel<<<P, 512, SMEM>>>(msm, refm, srcm, out_score, out_corr);
}